// round 7
// baseline (speedup 1.0000x reference)
#include <cuda_runtime.h>
#include <cstdint>

#define BLOCK 128
#define MTILE 32
#define MM 16
#define NMAX 8192
#define CHUNK 64
#define HALF_LN2 0.34657359027997264f
#define EPS_S 4e-6f
#define VSTR 9

// prologue-packed operands
__device__ uint2 g_b[(NMAX / 2) * MM];   // {hi,lo} bf16x2 of (0.5*ln2*coeff) pairs
__device__ uint2 g_v[NMAX * VSTR];       // tf32 {hi,lo} of v(y) = (|y|^2+eps, 1, y0, y1, y2), slots 5..8 zero

__device__ __forceinline__ uint32_t pack_bf16x2(float lo, float hi) {
    uint32_t d;
    asm("cvt.rn.bf16x2.f32 %0, %1, %2;" : "=r"(d) : "f"(hi), "f"(lo));
    return d;
}

__device__ __forceinline__ void split2(float f0, float f1, uint32_t& hi, uint32_t& lo) {
    hi = pack_bf16x2(f0, f1);
    float h0 = __uint_as_float(hi << 16);
    float h1 = __uint_as_float(hi & 0xffff0000u);
    lo = pack_bf16x2(f0 - h0, f1 - h1);
}

__device__ __forceinline__ uint32_t f2tf32(float f) {
    uint32_t u;
    asm("cvt.rna.tf32.f32 %0, %1;" : "=r"(u) : "f"(f));
    return u;
}

__device__ __forceinline__ void mma_bf16(float* c, const uint32_t* a, uint32_t b0, uint32_t b1) {
    asm volatile(
        "mma.sync.aligned.m16n8k16.row.col.f32.bf16.bf16.f32 "
        "{%0,%1,%2,%3}, {%4,%5,%6,%7}, {%8,%9}, {%0,%1,%2,%3};"
        : "+f"(c[0]), "+f"(c[1]), "+f"(c[2]), "+f"(c[3])
        : "r"(a[0]), "r"(a[1]), "r"(a[2]), "r"(a[3]), "r"(b0), "r"(b1));
}

// d = a*b + c  (separate C-in; used with zero constants for the first product)
__device__ __forceinline__ void mma_tf32_init(float* d, const uint32_t* a, uint32_t b0, uint32_t b1,
                                              float z0, float z1, float z2, float z3) {
    asm volatile(
        "mma.sync.aligned.m16n8k8.row.col.f32.tf32.tf32.f32 "
        "{%0,%1,%2,%3}, {%4,%5,%6,%7}, {%8,%9}, {%10,%11,%12,%13};"
        : "=f"(d[0]), "=f"(d[1]), "=f"(d[2]), "=f"(d[3])
        : "r"(a[0]), "r"(a[1]), "r"(a[2]), "r"(a[3]), "r"(b0), "r"(b1),
          "f"(z0), "f"(z1), "f"(z2), "f"(z3));
}

__device__ __forceinline__ void mma_tf32_acc(float* c, const uint32_t* a, uint32_t b0, uint32_t b1) {
    asm volatile(
        "mma.sync.aligned.m16n8k8.row.col.f32.tf32.tf32.f32 "
        "{%0,%1,%2,%3}, {%4,%5,%6,%7}, {%8,%9}, {%0,%1,%2,%3};"
        : "+f"(c[0]), "+f"(c[1]), "+f"(c[2]), "+f"(c[3])
        : "r"(a[0]), "r"(a[1]), "r"(a[2]), "r"(a[3]), "r"(b0), "r"(b1));
}

__device__ __forceinline__ uint32_t smem_u32(const void* p) {
    uint32_t a;
    asm("{ .reg .u64 t; cvta.to.shared.u64 t, %1; cvt.u32.u64 %0, t; }" : "=r"(a) : "l"(p));
    return a;
}

#define CP16(dst_u32, src_ptr) \
    asm volatile("cp.async.cg.shared.global [%0], [%1], 16;" :: "r"(dst_u32), "l"(src_ptr))

// ---------------- prologue ----------------
__global__ void prep_kernel(const float* __restrict__ y,
                            const float* __restrict__ coeffs,
                            int n, int npad) {
    int i = blockIdx.x * blockDim.x + threadIdx.x;
    if (i < npad) {
        float v[5];
        if (i < n) {
            float a = y[3 * i], b = y[3 * i + 1], c = y[3 * i + 2];
            v[0] = fmaf(a, a, fmaf(b, b, c * c)) + EPS_S;
            v[1] = 1.f; v[2] = a; v[3] = b; v[4] = c;
        } else {
            v[0] = 1.f; v[1] = 1.f; v[2] = 0.f; v[3] = 0.f; v[4] = 0.f;
        }
#pragma unroll
        for (int k = 0; k < VSTR; ++k) {
            uint2 o = make_uint2(0u, 0u);
            if (k < 5) {
                uint32_t h = f2tf32(v[k]);
                o.x = h;
                o.y = f2tf32(v[k] - __uint_as_float(h));
            }
            g_v[(size_t)i * VSTR + k] = o;
        }
    }
    int npe = (npad >> 1) * MM;
    if (i < npe) {
        int p = i >> 4, c = i & 15;
        int j0 = 2 * p, j1 = 2 * p + 1;
        float f0 = (j0 < n) ? HALF_LN2 * coeffs[(size_t)j0 * MM + c] : 0.f;
        float f1 = (j1 < n) ? HALF_LN2 * coeffs[(size_t)j1 * MM + c] : 0.f;
        uint32_t hi, lo;
        split2(f0, f1, hi, lo);
        g_b[i] = make_uint2(hi, lo);
    }
}

// ---------------- main kernel ----------------
__global__ __launch_bounds__(BLOCK) void rbf_tps_mma_kernel(
    const float* __restrict__ x,
    const float* __restrict__ shift,
    const float* __restrict__ scale,
    const float* __restrict__ coeffs,
    const int*   __restrict__ powers,
    float* __restrict__ out,
    int nx, int n, int npad, int r)
{
    __shared__ uint2 sb[2][(CHUNK / 2) * MM];   // 4 KB each, XOR-swizzled
    __shared__ uint2 sv[2][CHUNK * VSTR];       // 4.5 KB each, stride-9 rows
    __shared__ float sred[3][32][MM];

    const int tid  = threadIdx.x;
    const int lane = tid & 31;
    const int w    = tid >> 5;
    const int t4   = lane & 3;
    const int g    = lane >> 2;

    const int tilebase = blockIdx.x * MTILE;

    // rows g, g+8, g+16, g+24
    float4 xr[4];
#pragma unroll
    for (int i = 0; i < 4; ++i) {
        int row = tilebase + g + 8 * i;
        float4 v = make_float4(0.f, 0.f, 0.f, 0.f);
        if (row < nx) {
            v.x = x[3 * row + 0];
            v.y = x[3 * row + 1];
            v.z = x[3 * row + 2];
            v.w = fmaf(v.x, v.x, fmaf(v.y, v.y, v.z * v.z));
        }
        xr[i] = v;
    }

    // loop-invariant U fragments: u(x) = (1, |x|^2, -2x0, -2x1, -2x2, 0,0,0)
    // a0 = (row r,  k=t4), a1 = (row r+8, k=t4), a2 = (row r, k=t4+4), a3 = (row r+8, k=t4+4)
    uint32_t Uh[2][4], Ul[2][4];
#pragma unroll
    for (int rt = 0; rt < 2; ++rt) {
#pragma unroll
        for (int half = 0; half < 2; ++half) {
            float4 X = xr[2 * rt + half];
            float uk  = (t4 == 0) ? 1.f : (t4 == 1) ? X.w : (t4 == 2) ? -2.f * X.x : -2.f * X.y;
            float uk4 = (t4 == 0) ? -2.f * X.z : 0.f;
            uint32_t h1 = f2tf32(uk);
            Uh[rt][half] = h1;
            Ul[rt][half] = f2tf32(uk - __uint_as_float(h1));
            uint32_t h2 = f2tf32(uk4);
            Uh[rt][2 + half] = h2;
            Ul[rt][2 + half] = f2tf32(uk4 - __uint_as_float(h2));
        }
    }

    float acc[2][2][4];
#pragma unroll
    for (int a = 0; a < 2; ++a)
#pragma unroll
        for (int b = 0; b < 2; ++b)
#pragma unroll
            for (int c = 0; c < 4; ++c) acc[a][b][c] = 0.f;

    const int nchunks = npad / CHUNK;   // even (npad % 128 == 0)

    // lane-constant swizzled bf16-B column indices
    const int csw0 = g ^ ((t4 & 2) << 2);
    const int csw1 = (g + 8) ^ ((t4 & 2) << 2);
    const int p0   = w * 8 + t4;        // bf16 B pair base for this warp's 16 j

#define PREFETCH(c0, buf)                                                                  \
    do {                                                                                   \
        _Pragma("unroll")                                                                  \
        for (int q = 0; q < 2; ++q) {                                                      \
            int flat = (tid + q * 128) * 2;                                                \
            int p = flat >> 4, c = flat & 15;                                              \
            int dsti = p * 16 + (c ^ (((p >> 1) & 1) << 3));                               \
            CP16(smem_u32(&sb[buf][dsti]),                                                 \
                 &g_b[(size_t)(c0) * (CHUNK / 2) * MM + flat]);                            \
        }                                                                                  \
        _Pragma("unroll")                                                                  \
        for (int q = 0; q < 3; ++q) {                                                      \
            int idx = tid + q * 128;                                                       \
            if (idx < (CHUNK * VSTR) / 2)                                                  \
                CP16(smem_u32(&sv[buf][idx * 2]),                                          \
                     &g_v[(size_t)(c0) * CHUNK * VSTR + idx * 2]);                         \
        }                                                                                  \
        asm volatile("cp.async.commit_group;" ::: "memory");                               \
    } while (0)

#define DO_CHUNK(buf)                                                                      \
    do {                                                                                   \
        const int jbl = w * 16;                                                            \
        uint2 v00 = sv[buf][(jbl + g) * VSTR + t4];                                        \
        uint2 v01 = sv[buf][(jbl + g) * VSTR + t4 + 4];                                    \
        uint2 v10 = sv[buf][(jbl + 8 + g) * VSTR + t4];                                    \
        uint2 v11 = sv[buf][(jbl + 8 + g) * VSTR + t4 + 4];                                \
        uint2 b00 = sb[buf][p0 * MM + csw0];                                               \
        uint2 b01 = sb[buf][(p0 + 4) * MM + csw0];                                         \
        uint2 b10 = sb[buf][p0 * MM + csw1];                                               \
        uint2 b11 = sb[buf][(p0 + 4) * MM + csw1];                                         \
        _Pragma("unroll")                                                                  \
        for (int rt = 0; rt < 2; ++rt) {                                                   \
            float s0[4], s1[4];                                                            \
            mma_tf32_init(s0, Uh[rt], v00.x, v01.x, 0.f, 0.f, 0.f, 0.f);                   \
            mma_tf32_acc(s0, Ul[rt], v00.x, v01.x);                                        \
            mma_tf32_acc(s0, Uh[rt], v00.y, v01.y);                                        \
            mma_tf32_init(s1, Uh[rt], v10.x, v11.x, 0.f, 0.f, 0.f, 0.f);                   \
            mma_tf32_acc(s1, Ul[rt], v10.x, v11.x);                                        \
            mma_tf32_acc(s1, Uh[rt], v10.y, v11.y);                                        \
            float p00 = s0[0] * __log2f(fabsf(s0[0]));                                     \
            float p01 = s0[1] * __log2f(fabsf(s0[1]));                                     \
            float p02 = s0[2] * __log2f(fabsf(s0[2]));                                     \
            float p03 = s0[3] * __log2f(fabsf(s0[3]));                                     \
            float p10 = s1[0] * __log2f(fabsf(s1[0]));                                     \
            float p11 = s1[1] * __log2f(fabsf(s1[1]));                                     \
            float p12 = s1[2] * __log2f(fabsf(s1[2]));                                     \
            float p13 = s1[3] * __log2f(fabsf(s1[3]));                                     \
            uint32_t ah[4], al[4];                                                         \
            split2(p00, p01, ah[0], al[0]);                                                \
            split2(p02, p03, ah[1], al[1]);                                                \
            split2(p10, p11, ah[2], al[2]);                                                \
            split2(p12, p13, ah[3], al[3]);                                                \
            mma_bf16(acc[rt][0], ah, b00.x, b01.x);                                        \
            mma_bf16(acc[rt][0], al, b00.x, b01.x);                                        \
            mma_bf16(acc[rt][0], ah, b00.y, b01.y);                                        \
            mma_bf16(acc[rt][1], ah, b10.x, b11.x);                                        \
            mma_bf16(acc[rt][1], al, b10.x, b11.x);                                        \
            mma_bf16(acc[rt][1], ah, b10.y, b11.y);                                        \
        }                                                                                  \
    } while (0)

    PREFETCH(0, 0);
    PREFETCH(1, 1);

    for (int t = 0; t < nchunks; t += 2) {
        asm volatile("cp.async.wait_group 1;" ::: "memory");
        __syncthreads();
        DO_CHUNK(0);
        __syncthreads();
        if (t + 2 < nchunks) PREFETCH(t + 2, 0);
        else asm volatile("cp.async.commit_group;" ::: "memory");

        asm volatile("cp.async.wait_group 1;" ::: "memory");
        __syncthreads();
        DO_CHUNK(1);
        __syncthreads();
        if (t + 3 < nchunks) PREFETCH(t + 3, 1);
        else asm volatile("cp.async.commit_group;" ::: "memory");
    }
    asm volatile("cp.async.wait_group 0;" ::: "memory");

    // ---- 4-way j combine ----
    if (w > 0) {
#pragma unroll
        for (int rt = 0; rt < 2; ++rt)
#pragma unroll
            for (int nt = 0; nt < 2; ++nt)
#pragma unroll
                for (int q = 0; q < 4; ++q)
                    sred[w - 1][lane][rt * 8 + nt * 4 + q] = acc[rt][nt][q];
    }
    __syncthreads();
    if (w > 0) return;

#pragma unroll
    for (int ww = 0; ww < 3; ++ww)
#pragma unroll
        for (int rt = 0; rt < 2; ++rt)
#pragma unroll
            for (int nt = 0; nt < 2; ++nt)
#pragma unroll
                for (int q = 0; q < 4; ++q)
                    acc[rt][nt][q] += sred[ww][lane][rt * 8 + nt * 4 + q];

    // ---- epilogue: polynomial part (unscaled coeffs) + store ----
    // acc fragment: acc[rt][nt][q]: row = g + 16*rt + 8*(q>>1), col = 2*t4 + 8*nt + (q&1)
    const float sh0 = __ldg(&shift[0]), sh1 = __ldg(&shift[1]), sh2 = __ldg(&shift[2]);
    const float sl0 = __ldg(&scale[0]), sl1 = __ldg(&scale[1]), sl2 = __ldg(&scale[2]);

#pragma unroll
    for (int i = 0; i < 4; ++i) {
        int grow = tilebase + g + 8 * i;
        if (grow >= nx) continue;
        float4 xc = xr[i];
        float xh0 = (xc.x - sh0) / sl0;
        float xh1 = (xc.y - sh1) / sl1;
        float xh2 = (xc.z - sh2) / sl2;
        const int rt = i >> 1, up = i & 1;

#pragma unroll
        for (int nt = 0; nt < 2; ++nt) {
            const int col = 2 * t4 + 8 * nt;
            float o0 = acc[rt][nt][up * 2 + 0];
            float o1 = acc[rt][nt][up * 2 + 1];
            for (int k = 0; k < r; ++k) {
                float p = 1.f;
                int e0 = __ldg(&powers[k * 3 + 0]);
                int e1 = __ldg(&powers[k * 3 + 1]);
                int e2 = __ldg(&powers[k * 3 + 2]);
                for (int q = 0; q < e0; ++q) p *= xh0;
                for (int q = 0; q < e1; ++q) p *= xh1;
                for (int q = 0; q < e2; ++q) p *= xh2;
                float cc0 = __ldg(&coeffs[(size_t)(n + k) * MM + col]);
                float cc1 = __ldg(&coeffs[(size_t)(n + k) * MM + col + 1]);
                o0 = fmaf(p, cc0, o0);
                o1 = fmaf(p, cc1, o1);
            }
            *reinterpret_cast<float2*>(&out[(size_t)grow * MM + col]) = make_float2(o0, o1);
        }
    }
}

extern "C" void kernel_launch(void* const* d_in, const int* in_sizes, int n_in,
                              void* d_out, int out_size) {
    const float* x      = (const float*)d_in[0];
    const float* y      = (const float*)d_in[1];
    const float* shift  = (const float*)d_in[2];
    const float* scale  = (const float*)d_in[3];
    const float* coeffs = (const float*)d_in[4];
    const int*   powers = (const int*)d_in[5];

    int nx = in_sizes[0] / 3;
    int n  = in_sizes[1] / 3;
    int r  = in_sizes[5] / 3;

    int npad = (n + 255) & ~255;
    if (npad > NMAX) npad = NMAX;

    int prep_work = (npad >> 1) * MM;
    if (npad > prep_work) prep_work = npad;
    prep_kernel<<<(prep_work + 255) / 256, 256>>>(y, coeffs, n, npad);

    int grid = (nx + MTILE - 1) / MTILE;
    rbf_tps_mma_kernel<<<grid, BLOCK>>>(x, shift, scale, coeffs, powers,
                                        (float*)d_out, nx, n, npad, r);
}

// round 8
// speedup vs baseline: 1.4371x; 1.4371x over previous
#include <cuda_runtime.h>
#include <cstdint>

#define BLOCK 128
#define MTILE 32
#define MM 16
#define NMAX 8192
#define CHUNK 128
#define HALF_LN2 0.34657359027997264f
#define EPS_S 1e-5f

// prologue-packed operands
__device__ float4   g_y4[NMAX];             // (-2yx, -2yy, -2yz, |y|^2 + eps); pad = (0,0,0,1)
__device__ uint32_t g_b[(NMAX / 2) * MM];   // f16x2(0.5*ln2*c[2p][col], 0.5*ln2*c[2p+1][col])

__device__ __forceinline__ uint32_t pack_f16x2(float lo, float hi) {
    uint32_t d;
    asm("cvt.rn.f16x2.f32 %0, %1, %2;" : "=r"(d) : "f"(hi), "f"(lo));
    return d;
}

__device__ __forceinline__ void mma_f16(float* c, const uint32_t* a, uint32_t b0, uint32_t b1) {
    asm volatile(
        "mma.sync.aligned.m16n8k16.row.col.f32.f16.f16.f32 "
        "{%0,%1,%2,%3}, {%4,%5,%6,%7}, {%8,%9}, {%0,%1,%2,%3};"
        : "+f"(c[0]), "+f"(c[1]), "+f"(c[2]), "+f"(c[3])
        : "r"(a[0]), "r"(a[1]), "r"(a[2]), "r"(a[3]), "r"(b0), "r"(b1));
}

// phi-scaled A value = s * lg2(|s|); the 0.5*ln2 factor lives in B.
// y pre-packed as (-2y, |y|^2+eps) so s = |x|^2 + (u.v chain) > 0.
__device__ __forceinline__ float phi_f(float4 xr, float4 v) {
    float t = fmaf(xr.x, v.x, fmaf(xr.y, v.y, fmaf(xr.z, v.z, v.w)));
    float s = xr.w + t;
    return s * __log2f(fabsf(s));
}

__device__ __forceinline__ uint32_t smem_u32(const void* p) {
    uint32_t a;
    asm("{ .reg .u64 t; cvta.to.shared.u64 t, %1; cvt.u32.u64 %0, t; }" : "=r"(a) : "l"(p));
    return a;
}

#define CP16(dst_u32, src_ptr) \
    asm volatile("cp.async.cg.shared.global [%0], [%1], 16;" :: "r"(dst_u32), "l"(src_ptr))

// ---------------- prologue ----------------
__global__ void prep_kernel(const float* __restrict__ y,
                            const float* __restrict__ coeffs,
                            int n, int npad) {
    int i = blockIdx.x * blockDim.x + threadIdx.x;
    if (i < npad) {
        float4 v = make_float4(0.f, 0.f, 0.f, 1.f);
        if (i < n) {
            float a = y[3 * i], b = y[3 * i + 1], c = y[3 * i + 2];
            v = make_float4(-2.f * a, -2.f * b, -2.f * c,
                            fmaf(a, a, fmaf(b, b, c * c)) + EPS_S);
        }
        g_y4[i] = v;
    }
    int npe = (npad >> 1) * MM;
    if (i < npe) {
        int p = i >> 4, c = i & 15;
        int j0 = 2 * p, j1 = 2 * p + 1;
        float f0 = (j0 < n) ? HALF_LN2 * coeffs[(size_t)j0 * MM + c] : 0.f;
        float f1 = (j1 < n) ? HALF_LN2 * coeffs[(size_t)j1 * MM + c] : 0.f;
        g_b[i] = pack_f16x2(f0, f1);
    }
}

// ---------------- main kernel ----------------
__global__ __launch_bounds__(BLOCK, 6) void rbf_tps_mma_kernel(
    const float* __restrict__ x,
    const float* __restrict__ shift,
    const float* __restrict__ scale,
    const float* __restrict__ coeffs,
    const int*   __restrict__ powers,
    float* __restrict__ out,
    int nx, int n, int npad, int r)
{
    __shared__ float4   sy[2][CHUNK];               // 4 KB
    __shared__ uint32_t sb[2][(CHUNK / 2) * MM];    // 8 KB, XOR-swizzled cols
    __shared__ float    sred[3][32][MM];            // 6 KB

    const int tid  = threadIdx.x;
    const int lane = tid & 31;
    const int w    = tid >> 5;
    const int t4   = lane & 3;
    const int g    = lane >> 2;

    const int tilebase = blockIdx.x * MTILE;

    // rows g, g+8, g+16, g+24 of this 32-row tile
    float4 xr[4];
#pragma unroll
    for (int i = 0; i < 4; ++i) {
        int row = tilebase + g + 8 * i;
        float4 v = make_float4(0.f, 0.f, 0.f, 0.f);
        if (row < nx) {
            v.x = x[3 * row + 0];
            v.y = x[3 * row + 1];
            v.z = x[3 * row + 2];
            v.w = fmaf(v.x, v.x, fmaf(v.y, v.y, v.z * v.z));
        }
        xr[i] = v;
    }

    float acc[2][2][4];
#pragma unroll
    for (int a = 0; a < 2; ++a)
#pragma unroll
        for (int b = 0; b < 2; ++b)
#pragma unroll
            for (int c = 0; c < 4; ++c) acc[a][b][c] = 0.f;

    const int nchunks = npad / CHUNK;   // even (npad % 256 == 0)

    // lane-constant swizzled B column indices (conflict-free LDS.32)
    const int csw0 = g ^ ((t4 & 2) << 2);
    const int csw1 = (g + 8) ^ ((t4 & 2) << 2);

#define PREFETCH(c0, buf)                                                          \
    do {                                                                           \
        CP16(smem_u32(&sy[buf][tid]), &g_y4[(c0) * CHUNK + tid]);                  \
        _Pragma("unroll")                                                          \
        for (int q = 0; q < 2; ++q) {                                              \
            int qq = tid * 2 + q;              /* 16B unit, 0..255 */              \
            int p = qq >> 2;                   /* pair row */                      \
            int c = (qq & 3) * 4;              /* col group */                     \
            int dsti = p * 16 + (c ^ (((p >> 1) & 1) << 3));                       \
            CP16(smem_u32(&sb[buf][dsti]),                                         \
                 &g_b[(size_t)(c0) * (CHUNK / 2) * MM + qq * 4]);                  \
        }                                                                          \
        asm volatile("cp.async.commit_group;" ::: "memory");                       \
    } while (0)

#define DO_CHUNK(buf)                                                              \
    do {                                                                           \
        _Pragma("unroll")                                                          \
        for (int kk = 0; kk < 2; ++kk) {                                           \
            const int jbl = w * 32 + kk * 16;                                      \
            const int j0l = jbl + 2 * t4;                                          \
            float4 v0 = sy[buf][j0l];                                              \
            float4 v1 = sy[buf][j0l + 1];                                          \
            float4 v2 = sy[buf][j0l + 8];                                          \
            float4 v3 = sy[buf][j0l + 9];                                          \
            const int p0 = (jbl >> 1) + t4;                                        \
            uint32_t b00 = sb[buf][p0 * MM + csw0];                                \
            uint32_t b01 = sb[buf][(p0 + 4) * MM + csw0];                          \
            uint32_t b10 = sb[buf][p0 * MM + csw1];                                \
            uint32_t b11 = sb[buf][(p0 + 4) * MM + csw1];                          \
            _Pragma("unroll")                                                      \
            for (int rt = 0; rt < 2; ++rt) {                                       \
                float4 xa = xr[2 * rt], xb = xr[2 * rt + 1];                       \
                float p00 = phi_f(xa, v0), p01 = phi_f(xa, v1);                    \
                float p02 = phi_f(xa, v2), p03 = phi_f(xa, v3);                    \
                float p10 = phi_f(xb, v0), p11 = phi_f(xb, v1);                    \
                float p12 = phi_f(xb, v2), p13 = phi_f(xb, v3);                    \
                uint32_t ah[4];                                                    \
                ah[0] = pack_f16x2(p00, p01);                                      \
                ah[1] = pack_f16x2(p10, p11);                                      \
                ah[2] = pack_f16x2(p02, p03);                                      \
                ah[3] = pack_f16x2(p12, p13);                                      \
                mma_f16(acc[rt][0], ah, b00, b01);                                 \
                mma_f16(acc[rt][1], ah, b10, b11);                                 \
            }                                                                      \
        }                                                                          \
    } while (0)

    PREFETCH(0, 0);
    PREFETCH(1, 1);

    for (int t = 0; t < nchunks; t += 2) {
        asm volatile("cp.async.wait_group 1;" ::: "memory");
        __syncthreads();
        DO_CHUNK(0);
        __syncthreads();
        if (t + 2 < nchunks) PREFETCH(t + 2, 0);
        else asm volatile("cp.async.commit_group;" ::: "memory");

        asm volatile("cp.async.wait_group 1;" ::: "memory");
        __syncthreads();
        DO_CHUNK(1);
        __syncthreads();
        if (t + 3 < nchunks) PREFETCH(t + 3, 1);
        else asm volatile("cp.async.commit_group;" ::: "memory");
    }
    asm volatile("cp.async.wait_group 0;" ::: "memory");

    // ---- 4-way j combine: warps 1-3 publish, warp 0 reduces ----
    if (w > 0) {
#pragma unroll
        for (int rt = 0; rt < 2; ++rt)
#pragma unroll
            for (int nt = 0; nt < 2; ++nt)
#pragma unroll
                for (int q = 0; q < 4; ++q)
                    sred[w - 1][lane][rt * 8 + nt * 4 + q] = acc[rt][nt][q];
    }
    __syncthreads();
    if (w > 0) return;

#pragma unroll
    for (int ww = 0; ww < 3; ++ww)
#pragma unroll
        for (int rt = 0; rt < 2; ++rt)
#pragma unroll
            for (int nt = 0; nt < 2; ++nt)
#pragma unroll
                for (int q = 0; q < 4; ++q)
                    acc[rt][nt][q] += sred[ww][lane][rt * 8 + nt * 4 + q];

    // ---- epilogue: polynomial part (unscaled coeffs) + store ----
    const float sh0 = __ldg(&shift[0]), sh1 = __ldg(&shift[1]), sh2 = __ldg(&shift[2]);
    const float sl0 = __ldg(&scale[0]), sl1 = __ldg(&scale[1]), sl2 = __ldg(&scale[2]);

#pragma unroll
    for (int i = 0; i < 4; ++i) {
        int grow = tilebase + g + 8 * i;
        if (grow >= nx) continue;
        float4 xc = xr[i];
        float xh0 = (xc.x - sh0) / sl0;
        float xh1 = (xc.y - sh1) / sl1;
        float xh2 = (xc.z - sh2) / sl2;
        const int rt = i >> 1, up = i & 1;

#pragma unroll
        for (int nt = 0; nt < 2; ++nt) {
            const int col = 2 * t4 + 8 * nt;
            float o0 = acc[rt][nt][up * 2 + 0];
            float o1 = acc[rt][nt][up * 2 + 1];
            for (int k = 0; k < r; ++k) {
                float p = 1.f;
                int e0 = __ldg(&powers[k * 3 + 0]);
                int e1 = __ldg(&powers[k * 3 + 1]);
                int e2 = __ldg(&powers[k * 3 + 2]);
                for (int q = 0; q < e0; ++q) p *= xh0;
                for (int q = 0; q < e1; ++q) p *= xh1;
                for (int q = 0; q < e2; ++q) p *= xh2;
                float cc0 = __ldg(&coeffs[(size_t)(n + k) * MM + col]);
                float cc1 = __ldg(&coeffs[(size_t)(n + k) * MM + col + 1]);
                o0 = fmaf(p, cc0, o0);
                o1 = fmaf(p, cc1, o1);
            }
            *reinterpret_cast<float2*>(&out[(size_t)grow * MM + col]) = make_float2(o0, o1);
        }
    }
}

extern "C" void kernel_launch(void* const* d_in, const int* in_sizes, int n_in,
                              void* d_out, int out_size) {
    const float* x      = (const float*)d_in[0];
    const float* y      = (const float*)d_in[1];
    const float* shift  = (const float*)d_in[2];
    const float* scale  = (const float*)d_in[3];
    const float* coeffs = (const float*)d_in[4];
    const int*   powers = (const int*)d_in[5];

    int nx = in_sizes[0] / 3;
    int n  = in_sizes[1] / 3;
    int r  = in_sizes[5] / 3;

    int npad = (n + 255) & ~255;     // even number of 128-chunks
    if (npad > NMAX) npad = NMAX;

    int prep_work = (npad >> 1) * MM;
    if (npad > prep_work) prep_work = npad;
    prep_kernel<<<(prep_work + 255) / 256, 256>>>(y, coeffs, n, npad);

    int grid = (nx + MTILE - 1) / MTILE;
    rbf_tps_mma_kernel<<<grid, BLOCK>>>(x, shift, scale, coeffs, powers,
                                        (float*)d_out, nx, n, npad, r);
}

// round 9
// speedup vs baseline: 1.7295x; 1.2035x over previous
#include <cuda_runtime.h>
#include <cstdint>

#define BLOCK 128
#define MTILE 32
#define MM 16
#define NMAX 8192
#define CHUNK 128
#define HALF_LN2 0.34657359027997264f
#define EPS_S 1e-5f

typedef unsigned long long ull;

// prologue-packed operands
// g_yp: per j-pair p (j0=2p, j1=2p+1): [2p]   = (x0, x1, y0, y1)
//                                      [2p+1] = (z0, z1, w0+eps, w1+eps)  (w=|y|^2)
__device__ float4   g_yp[NMAX];
__device__ uint32_t g_b[(NMAX / 2) * MM];   // f16x2(0.5*ln2*c[2p][col], 0.5*ln2*c[2p+1][col])

__device__ __forceinline__ uint32_t pack_f16x2(float lo, float hi) {
    uint32_t d;
    asm("cvt.rn.f16x2.f32 %0, %1, %2;" : "=r"(d) : "f"(hi), "f"(lo));
    return d;
}

// ---- packed f32x2 helpers (Blackwell FFMA2 path) ----
__device__ __forceinline__ ull fma2(ull a, ull b, ull c) {
    ull d;
    asm("fma.rn.f32x2 %0, %1, %2, %3;" : "=l"(d) : "l"(a), "l"(b), "l"(c));
    return d;
}
__device__ __forceinline__ ull add2(ull a, ull b) {
    ull d;
    asm("add.rn.f32x2 %0, %1, %2;" : "=l"(d) : "l"(a), "l"(b));
    return d;
}
__device__ __forceinline__ ull mul2(ull a, ull b) {
    ull d;
    asm("mul.rn.f32x2 %0, %1, %2;" : "=l"(d) : "l"(a), "l"(b));
    return d;
}
__device__ __forceinline__ ull dup2(float v) {
    ull d;
    uint32_t b = __float_as_uint(v);
    asm("mov.b64 %0, {%1, %2};" : "=l"(d) : "r"(b), "r"(b));
    return d;
}
__device__ __forceinline__ ull pk2(float lo, float hi) {
    ull d;
    asm("mov.b64 %0, {%1, %2};" : "=l"(d) : "r"(__float_as_uint(lo)), "r"(__float_as_uint(hi)));
    return d;
}
__device__ __forceinline__ float2 unpk(ull p) {
    uint32_t lo, hi;
    asm("mov.b64 {%0, %1}, %2;" : "=r"(lo), "=r"(hi) : "l"(p));
    return make_float2(__uint_as_float(lo), __uint_as_float(hi));
}

struct XP { ull x, y, z, w; };   // duplicated (v,v) per component; w = |x|^2

// phi for a j-pair against one x row, returned as f16x2 A-fragment word.
// s = |x|^2 + (-2x.y) + |y|^2(+eps); A value = s*lg2|s| (0.5*ln2 in B).
__device__ __forceinline__ uint32_t phi2pack(const XP& X, ulonglong2 a, ulonglong2 b) {
    ull c0 = add2(b.y, X.w);
    ull c1 = fma2(X.z, b.x, c0);
    ull c2 = fma2(X.y, a.y, c1);
    ull s  = fma2(X.x, a.x, c2);
    float2 sf = unpk(s);
    float l0 = __log2f(fabsf(sf.x));
    float l1 = __log2f(fabsf(sf.y));
    float2 pf = unpk(mul2(s, pk2(l0, l1)));
    return pack_f16x2(pf.x, pf.y);
}

__device__ __forceinline__ void mma_f16(float* c, const uint32_t* a, uint32_t b0, uint32_t b1) {
    asm volatile(
        "mma.sync.aligned.m16n8k16.row.col.f32.f16.f16.f32 "
        "{%0,%1,%2,%3}, {%4,%5,%6,%7}, {%8,%9}, {%0,%1,%2,%3};"
        : "+f"(c[0]), "+f"(c[1]), "+f"(c[2]), "+f"(c[3])
        : "r"(a[0]), "r"(a[1]), "r"(a[2]), "r"(a[3]), "r"(b0), "r"(b1));
}

__device__ __forceinline__ uint32_t smem_u32(const void* p) {
    uint32_t a;
    asm("{ .reg .u64 t; cvta.to.shared.u64 t, %1; cvt.u32.u64 %0, t; }" : "=r"(a) : "l"(p));
    return a;
}

#define CP16(dst_u32, src_ptr) \
    asm volatile("cp.async.cg.shared.global [%0], [%1], 16;" :: "r"(dst_u32), "l"(src_ptr))

// ---------------- prologue ----------------
__global__ void prep_kernel(const float* __restrict__ y,
                            const float* __restrict__ coeffs,
                            int n, int npad) {
    int i = blockIdx.x * blockDim.x + threadIdx.x;
    int npairs = npad >> 1;
    if (i < npairs) {
        int j0 = 2 * i, j1 = 2 * i + 1;
        float a0 = 0.f, b0 = 0.f, c0 = 0.f, w0 = 1.f;
        float a1 = 0.f, b1 = 0.f, c1 = 0.f, w1 = 1.f;
        if (j0 < n) {
            a0 = y[3 * j0]; b0 = y[3 * j0 + 1]; c0 = y[3 * j0 + 2];
            w0 = fmaf(a0, a0, fmaf(b0, b0, c0 * c0)) + EPS_S;
            a0 = -2.f * a0; b0 = -2.f * b0; c0 = -2.f * c0;
        }
        if (j1 < n) {
            a1 = y[3 * j1]; b1 = y[3 * j1 + 1]; c1 = y[3 * j1 + 2];
            w1 = fmaf(a1, a1, fmaf(b1, b1, c1 * c1)) + EPS_S;
            a1 = -2.f * a1; b1 = -2.f * b1; c1 = -2.f * c1;
        }
        g_yp[2 * i + 0] = make_float4(a0, a1, b0, b1);
        g_yp[2 * i + 1] = make_float4(c0, c1, w0, w1);
    }
    int npe = npairs * MM;
    if (i < npe) {
        int p = i >> 4, c = i & 15;
        int j0 = 2 * p, j1 = 2 * p + 1;
        float f0 = (j0 < n) ? HALF_LN2 * coeffs[(size_t)j0 * MM + c] : 0.f;
        float f1 = (j1 < n) ? HALF_LN2 * coeffs[(size_t)j1 * MM + c] : 0.f;
        g_b[i] = pack_f16x2(f0, f1);
    }
}

// ---------------- main kernel ----------------
__global__ __launch_bounds__(BLOCK, 5) void rbf_tps_mma_kernel(
    const float* __restrict__ x,
    const float* __restrict__ shift,
    const float* __restrict__ scale,
    const float* __restrict__ coeffs,
    const int*   __restrict__ powers,
    float* __restrict__ out,
    int nx, int n, int npad, int r)
{
    __shared__ __align__(16) ulonglong2 sv[2][CHUNK];   // 4 KB: 64 pairs x 2 entries per buf
    __shared__ uint32_t sb[2][(CHUNK / 2) * MM];        // 8 KB, XOR-swizzled cols
    __shared__ float    sred[3][32][MM];                // 6 KB

    const int tid  = threadIdx.x;
    const int lane = tid & 31;
    const int w    = tid >> 5;
    const int t4   = lane & 3;
    const int g    = lane >> 2;

    const int tilebase = blockIdx.x * MTILE;

    // duplicated x operands for rows g, g+8, g+16, g+24
    XP Xd[4];
#pragma unroll
    for (int i = 0; i < 4; ++i) {
        int row = tilebase + g + 8 * i;
        float xx = 0.f, xy = 0.f, xz = 0.f;
        if (row < nx) {
            xx = x[3 * row + 0];
            xy = x[3 * row + 1];
            xz = x[3 * row + 2];
        }
        float x2 = fmaf(xx, xx, fmaf(xy, xy, xz * xz));
        Xd[i].x = dup2(xx);
        Xd[i].y = dup2(xy);
        Xd[i].z = dup2(xz);
        Xd[i].w = dup2(x2);
    }

    float acc[2][2][4];
#pragma unroll
    for (int a = 0; a < 2; ++a)
#pragma unroll
        for (int b = 0; b < 2; ++b)
#pragma unroll
            for (int c = 0; c < 4; ++c) acc[a][b][c] = 0.f;

    const int nchunks = npad / CHUNK;   // even (npad % 256 == 0)

    // lane-constant swizzled B column indices (conflict-free LDS.32)
    const int csw0 = g ^ ((t4 & 2) << 2);
    const int csw1 = (g + 8) ^ ((t4 & 2) << 2);

#define PREFETCH(c0, buf)                                                          \
    do {                                                                           \
        CP16(smem_u32(&sv[buf][tid]), &g_yp[(c0) * CHUNK + tid]);                  \
        _Pragma("unroll")                                                          \
        for (int q = 0; q < 2; ++q) {                                              \
            int qq = tid * 2 + q;              /* 16B unit, 0..255 */              \
            int p = qq >> 2;                   /* pair row */                      \
            int c = (qq & 3) * 4;              /* col group */                     \
            int dsti = p * 16 + (c ^ (((p >> 1) & 1) << 3));                       \
            CP16(smem_u32(&sb[buf][dsti]),                                         \
                 &g_b[(size_t)(c0) * (CHUNK / 2) * MM + qq * 4]);                  \
        }                                                                          \
        asm volatile("cp.async.commit_group;" ::: "memory");                       \
    } while (0)

#define DO_CHUNK(buf)                                                              \
    do {                                                                           \
        _Pragma("unroll")                                                          \
        for (int kk = 0; kk < 2; ++kk) {                                           \
            const int pp = w * 16 + kk * 8 + t4;   /* j-pair index in chunk */     \
            ulonglong2 va0 = sv[buf][2 * pp];                                      \
            ulonglong2 vb0 = sv[buf][2 * pp + 1];                                  \
            ulonglong2 va1 = sv[buf][2 * (pp + 4)];                                \
            ulonglong2 vb1 = sv[buf][2 * (pp + 4) + 1];                            \
            uint32_t b00 = sb[buf][pp * MM + csw0];                                \
            uint32_t b01 = sb[buf][(pp + 4) * MM + csw0];                          \
            uint32_t b10 = sb[buf][pp * MM + csw1];                                \
            uint32_t b11 = sb[buf][(pp + 4) * MM + csw1];                          \
            _Pragma("unroll")                                                      \
            for (int rt = 0; rt < 2; ++rt) {                                       \
                uint32_t ah[4];                                                    \
                ah[0] = phi2pack(Xd[2 * rt],     va0, vb0);                        \
                ah[1] = phi2pack(Xd[2 * rt + 1], va0, vb0);                        \
                ah[2] = phi2pack(Xd[2 * rt],     va1, vb1);                        \
                ah[3] = phi2pack(Xd[2 * rt + 1], va1, vb1);                        \
                mma_f16(acc[rt][0], ah, b00, b01);                                 \
                mma_f16(acc[rt][1], ah, b10, b11);                                 \
            }                                                                      \
        }                                                                          \
    } while (0)

    PREFETCH(0, 0);
    PREFETCH(1, 1);

    for (int t = 0; t < nchunks; t += 2) {
        asm volatile("cp.async.wait_group 1;" ::: "memory");
        __syncthreads();
        DO_CHUNK(0);
        __syncthreads();
        if (t + 2 < nchunks) PREFETCH(t + 2, 0);
        else asm volatile("cp.async.commit_group;" ::: "memory");

        asm volatile("cp.async.wait_group 1;" ::: "memory");
        __syncthreads();
        DO_CHUNK(1);
        __syncthreads();
        if (t + 3 < nchunks) PREFETCH(t + 3, 1);
        else asm volatile("cp.async.commit_group;" ::: "memory");
    }
    asm volatile("cp.async.wait_group 0;" ::: "memory");

    // ---- 4-way j combine: warps 1-3 publish, warp 0 reduces ----
    if (w > 0) {
#pragma unroll
        for (int rt = 0; rt < 2; ++rt)
#pragma unroll
            for (int nt = 0; nt < 2; ++nt)
#pragma unroll
                for (int q = 0; q < 4; ++q)
                    sred[w - 1][lane][rt * 8 + nt * 4 + q] = acc[rt][nt][q];
    }
    __syncthreads();
    if (w > 0) return;

#pragma unroll
    for (int ww = 0; ww < 3; ++ww)
#pragma unroll
        for (int rt = 0; rt < 2; ++rt)
#pragma unroll
            for (int nt = 0; nt < 2; ++nt)
#pragma unroll
                for (int q = 0; q < 4; ++q)
                    acc[rt][nt][q] += sred[ww][lane][rt * 8 + nt * 4 + q];

    // ---- epilogue: polynomial part (unscaled coeffs) + store ----
    const float sh0 = __ldg(&shift[0]), sh1 = __ldg(&shift[1]), sh2 = __ldg(&shift[2]);
    const float sl0 = __ldg(&scale[0]), sl1 = __ldg(&scale[1]), sl2 = __ldg(&scale[2]);

#pragma unroll
    for (int i = 0; i < 4; ++i) {
        int grow = tilebase + g + 8 * i;
        if (grow >= nx) continue;
        float xcx = unpk(Xd[i].x).x;
        float xcy = unpk(Xd[i].y).x;
        float xcz = unpk(Xd[i].z).x;
        float xh0 = (xcx - sh0) / sl0;
        float xh1 = (xcy - sh1) / sl1;
        float xh2 = (xcz - sh2) / sl2;
        const int rt = i >> 1, up = i & 1;

#pragma unroll
        for (int nt = 0; nt < 2; ++nt) {
            const int col = 2 * t4 + 8 * nt;
            float o0 = acc[rt][nt][up * 2 + 0];
            float o1 = acc[rt][nt][up * 2 + 1];
            for (int k = 0; k < r; ++k) {
                float p = 1.f;
                int e0 = __ldg(&powers[k * 3 + 0]);
                int e1 = __ldg(&powers[k * 3 + 1]);
                int e2 = __ldg(&powers[k * 3 + 2]);
                for (int q = 0; q < e0; ++q) p *= xh0;
                for (int q = 0; q < e1; ++q) p *= xh1;
                for (int q = 0; q < e2; ++q) p *= xh2;
                float cc0 = __ldg(&coeffs[(size_t)(n + k) * MM + col]);
                float cc1 = __ldg(&coeffs[(size_t)(n + k) * MM + col + 1]);
                o0 = fmaf(p, cc0, o0);
                o1 = fmaf(p, cc1, o1);
            }
            *reinterpret_cast<float2*>(&out[(size_t)grow * MM + col]) = make_float2(o0, o1);
        }
    }
}

extern "C" void kernel_launch(void* const* d_in, const int* in_sizes, int n_in,
                              void* d_out, int out_size) {
    const float* x      = (const float*)d_in[0];
    const float* y      = (const float*)d_in[1];
    const float* shift  = (const float*)d_in[2];
    const float* scale  = (const float*)d_in[3];
    const float* coeffs = (const float*)d_in[4];
    const int*   powers = (const int*)d_in[5];

    int nx = in_sizes[0] / 3;
    int n  = in_sizes[1] / 3;
    int r  = in_sizes[5] / 3;

    int npad = (n + 255) & ~255;     // even number of 128-chunks
    if (npad > NMAX) npad = NMAX;

    int prep_work = (npad >> 1) * MM;
    prep_kernel<<<(prep_work + 255) / 256, 256>>>(y, coeffs, n, npad);

    int grid = (nx + MTILE - 1) / MTILE;
    rbf_tps_mma_kernel<<<grid, BLOCK>>>(x, shift, scale, coeffs, powers,
                                        (float*)d_out, nx, n, npad, r);
}